// round 13
// baseline (speedup 1.0000x reference)
#include <cuda_runtime.h>
#include <cuda_bf16.h>
#include <cstdint>

// Problem constants
#define BB 2
#define SS 2048
#define DD 1024
#define HH 16
#define HD 64
#define D3 3072
#define MROWS (BB * SS)          // 4096
#define SCALE 0.03125f           // 1/sqrt(1024)
#define LOG2E 1.4426950408889634f
#define LN_EPS 1e-5f

// ---------------------------------------------------------------------------
// Scratch (no allocation allowed -> __device__ globals)
// ---------------------------------------------------------------------------
__device__ __nv_bfloat16 g_qkvb[MROWS * D3];   // 24 MB (QKV, bf16)
__device__ float g_y[MROWS * DD];              // 16 MB (proj + residual, fp32)
__device__ __nv_bfloat16 g_xb[MROWS * DD];     //  8 MB (x, bf16)
__device__ __nv_bfloat16 g_wb[D3 * DD];        //  6 MB (W_w, bf16)
__device__ __nv_bfloat16 g_pwb[DD * DD];       //  2 MB (proj_w, bf16)
__device__ __nv_bfloat16 g_ob[MROWS * DD];     //  8 MB (attention out, bf16)

// ---------------------------------------------------------------------------
// Portable helpers (sm_80+ only)
// ---------------------------------------------------------------------------
__device__ __forceinline__ uint32_t smem_u32(const void* p) {
    uint32_t a;
    asm("{ .reg .u64 t; cvta.to.shared.u64 t, %1; cvt.u32.u64 %0, t; }"
        : "=r"(a) : "l"(p));
    return a;
}

__device__ __forceinline__ void cp16(uint32_t dst, const void* src) {
    asm volatile("cp.async.ca.shared.global [%0], [%1], 16;"
                 :: "r"(dst), "l"(src) : "memory");
}
// L1-bypassing variant for the GEMM 3-stage pipeline (no L1 fill pressure)
__device__ __forceinline__ void cp16cg(uint32_t dst, const void* src) {
    asm volatile("cp.async.cg.shared.global [%0], [%1], 16;"
                 :: "r"(dst), "l"(src) : "memory");
}
#define CP_COMMIT() asm volatile("cp.async.commit_group;" ::: "memory")
#define CP_WAIT1()  asm volatile("cp.async.wait_group 1;" ::: "memory")
#define CP_WAIT0()  asm volatile("cp.async.wait_group 0;" ::: "memory")

__device__ __forceinline__ float ex2f(float x) {
    float r;
    asm("ex2.approx.f32 %0, %1;" : "=f"(r) : "f"(x));
    return r;
}

__device__ __forceinline__ void mma_bf16(
    float* c, const uint32_t* a, uint32_t b0, uint32_t b1)
{
    asm volatile(
        "mma.sync.aligned.m16n8k16.row.col.f32.bf16.bf16.f32 "
        "{%0,%1,%2,%3}, {%4,%5,%6,%7}, {%8,%9}, {%0,%1,%2,%3};"
        : "+f"(c[0]), "+f"(c[1]), "+f"(c[2]), "+f"(c[3])
        : "r"(a[0]), "r"(a[1]), "r"(a[2]), "r"(a[3]),
          "r"(b0), "r"(b1));
}

#define LDSM4(r0, r1, r2, r3, addr) \
    asm volatile("ldmatrix.sync.aligned.m8n8.x4.shared.b16 {%0,%1,%2,%3}, [%4];" \
        : "=r"(r0), "=r"(r1), "=r"(r2), "=r"(r3) : "r"(addr))

#define LDSM4T(r0, r1, r2, r3, addr) \
    asm volatile("ldmatrix.sync.aligned.m8n8.x4.trans.shared.b16 {%0,%1,%2,%3}, [%4];" \
        : "=r"(r0), "=r"(r1), "=r"(r2), "=r"(r3) : "r"(addr))

__device__ __forceinline__ uint32_t pack_bf16x2(float lo, float hi) {
    __nv_bfloat162 h = __floats2bfloat162_rn(lo, hi);
    return *(uint32_t*)&h;
}

// ---------------------------------------------------------------------------
// fp32 -> bf16 conversion, all three inputs in ONE launch
// ---------------------------------------------------------------------------
#define CVT_N4_X  (MROWS * DD / 4)
#define CVT_N4_W  (D3 * DD / 4)
#define CVT_N4_PW (DD * DD / 4)
#define CVT_N4_TOT (CVT_N4_X + CVT_N4_W + CVT_N4_PW)

__global__ __launch_bounds__(256) void cvt_bf16_all(
    const float* __restrict__ x, const float* __restrict__ w,
    const float* __restrict__ pw,
    __nv_bfloat16* __restrict__ xb, __nv_bfloat16* __restrict__ wb,
    __nv_bfloat16* __restrict__ pwb)
{
    int i = blockIdx.x * 256 + threadIdx.x;
    if (i >= CVT_N4_TOT) return;
    const float* in;
    __nv_bfloat16* out;
    if (i < CVT_N4_X)                 { in = x;  out = xb; }
    else if (i < CVT_N4_X + CVT_N4_W) { in = w;  out = wb;  i -= CVT_N4_X; }
    else                              { in = pw; out = pwb; i -= CVT_N4_X + CVT_N4_W; }
    float4 v = *(const float4*)(in + (size_t)i * 4);
    uint2 u;
    u.x = pack_bf16x2(v.x, v.y);
    u.y = pack_bf16x2(v.z, v.w);
    *(uint2*)(out + (size_t)i * 4) = u;
}

// ===========================================================================
// BF16 mma.sync GEMM: CTA 128x128, BK=64, 8 warps (4M x 2N), warp 32x64.
// 3-stage cp.async.cg pipeline -> ONE barrier per chunk; ldmatrix.x4; 144B rows.
// ===========================================================================
#define BKB 64
#define GROW 144
#define GT_BYTES (128 * GROW)          // 18432 per tile
#define GEMM_SMEM (6 * GT_BYTES)       // 110592 (3 stages x {A,B})

__global__ __launch_bounds__(256) void gemm_bf16(
    const __nv_bfloat16* __restrict__ A, const __nv_bfloat16* __restrict__ W,
    const float* __restrict__ bias, const float* __restrict__ resid,
    float* __restrict__ C, __nv_bfloat16* __restrict__ Cb,
    int M, int N, int K)
{
    extern __shared__ char smc[];
    const uint32_t sb = smem_u32(smc);
    const uint32_t sA[3] = { sb,            sb + 2 * GT_BYTES, sb + 4 * GT_BYTES };
    const uint32_t sB[3] = { sb + GT_BYTES, sb + 3 * GT_BYTES, sb + 5 * GT_BYTES };

    const int tid  = threadIdx.x;
    const int lane = tid & 31;
    const int wid  = tid >> 5;
    const int g    = lane >> 2;
    const int c    = lane & 3;
    const int wm0  = (wid & 3) * 32;
    const int wn0  = (wid >> 2) * 64;
    const int m0   = blockIdx.y * 128;
    const int n0   = blockIdx.x * 128;

    const uint32_t aOff = (uint32_t)(wm0 + (lane & 15)) * GROW + ((lane >> 4) * 16);
    const uint32_t bOff = (uint32_t)(wn0 + ((lane >> 4) << 3) + (lane & 7)) * GROW
                        + (((lane >> 3) & 1) * 16);

    float acc[2][8][4];
#pragma unroll
    for (int mt = 0; mt < 2; mt++)
#pragma unroll
        for (int nt = 0; nt < 8; nt++)
#pragma unroll
            for (int k = 0; k < 4; k++) acc[mt][nt][k] = 0.f;

    const int nch = K / BKB;

    auto load_chunk = [&](int i, int st) {
        const __nv_bfloat16* Ag = A + (size_t)m0 * K + i * BKB;
        const __nv_bfloat16* Wg = W + (size_t)n0 * K + i * BKB;
#pragma unroll
        for (int t = 0; t < 4; t++) {
            const int idx = tid + t * 256;
            const int row = idx >> 3;
            const int q   = idx & 7;
            const uint32_t off = (uint32_t)row * GROW + q * 16;
            cp16cg(sA[st] + off, Ag + (size_t)row * K + q * 8);
            cp16cg(sB[st] + off, Wg + (size_t)row * K + q * 8);
        }
        CP_COMMIT();
    };

    load_chunk(0, 0);
    load_chunk(1, 1);

    int st = 0;
    for (int i = 0; i < nch; i++) {
        CP_WAIT1();            // chunk i's group complete (2 groups in flight)
        __syncthreads();       // also protects stage overwritten 2 chunks ago
        if (i + 2 < nch) load_chunk(i + 2, st == 0 ? 2 : st - 1);
        else             CP_COMMIT();   // uniform group accounting

        const uint32_t aBase = sA[st] + aOff;
        const uint32_t bBase = sB[st] + bOff;
#pragma unroll
        for (int kk = 0; kk < 4; kk++) {
            uint32_t a0[4], a1[4];
            LDSM4(a0[0], a0[1], a0[2], a0[3], aBase + kk * 32);
            LDSM4(a1[0], a1[1], a1[2], a1[3], aBase + kk * 32 + 16 * GROW);
            uint32_t bq[4][4];
#pragma unroll
            for (int p = 0; p < 4; p++)
                LDSM4(bq[p][0], bq[p][1], bq[p][2], bq[p][3],
                      bBase + (uint32_t)p * 16 * GROW + kk * 32);
#pragma unroll
            for (int p = 0; p < 4; p++) {
                mma_bf16(acc[0][2 * p    ], a0, bq[p][0], bq[p][1]);
                mma_bf16(acc[0][2 * p + 1], a0, bq[p][2], bq[p][3]);
                mma_bf16(acc[1][2 * p    ], a1, bq[p][0], bq[p][1]);
                mma_bf16(acc[1][2 * p + 1], a1, bq[p][2], bq[p][3]);
            }
        }
        st = (st == 2) ? 0 : st + 1;
    }

    // Epilogue
#pragma unroll
    for (int mt = 0; mt < 2; mt++) {
#pragma unroll
        for (int hrow = 0; hrow < 2; hrow++) {
            const int m = m0 + wm0 + mt * 16 + g + hrow * 8;
#pragma unroll
            for (int nt = 0; nt < 8; nt++) {
                const int col = n0 + wn0 + nt * 8 + c * 2;
                float2 bi = *(const float2*)(bias + col);
                float2 v;
                v.x = acc[mt][nt][hrow * 2 + 0] + bi.x;
                v.y = acc[mt][nt][hrow * 2 + 1] + bi.y;
                if (resid) {
                    float2 r = *(const float2*)(resid + (size_t)m * N + col);
                    v.x += r.x; v.y += r.y;
                }
                if (Cb) {
                    uint32_t hh = pack_bf16x2(v.x, v.y);
                    *(uint32_t*)(Cb + (size_t)m * N + col) = hh;
                } else {
                    *(float2*)(C + (size_t)m * N + col) = v;
                }
            }
        }
    }
}

// ===========================================================================
// BF16 tensor-core flash attention (R10-proven, P in registers),
// heavy CTAs first (descending qt).
// ===========================================================================
#define AROW 144
#define QP_OFF 0
#define K_OFF  (64 * AROW)
#define V_OFF  (K_OFF + 2 * 64 * AROW)
#define BIA_OFF (V_OFF + 2 * 64 * AROW)
#define ATTN_SMEM (BIA_OFF + 2 * 128 * 4)  // 47104 bytes

__global__ __launch_bounds__(128) void attn_bf16(
    const __nv_bfloat16* __restrict__ qkv, const float* __restrict__ rpb,
    __nv_bfloat16* __restrict__ obuf)
{
    extern __shared__ char smc[];
    const uint32_t sb = smem_u32(smc);

    const int qt = (SS / 64 - 1) - blockIdx.x;
    const int h  = blockIdx.y;
    const int b  = blockIdx.z;
    const int tid = threadIdx.x;
    const int w    = tid >> 5;
    const int lane = tid & 31;
    const int g    = lane >> 2;
    const int c    = lane & 3;
    const int q0   = qt * 64;
    const int r0   = w * 16 + g;
    const int r1   = r0 + 8;
    const float CF = SCALE * LOG2E;

    // ---- Load Q tile ----
    {
        const __nv_bfloat16* Qg = qkv + (size_t)(b * SS + q0) * D3 + h * HD;
#pragma unroll
        for (int t = 0; t < 4; t++) {
            const int idx = tid + t * 128;
            const int row = idx >> 3, q = idx & 7;
            uint4 v = *(const uint4*)(Qg + (size_t)row * D3 + q * 8);
            *(uint4*)(smc + QP_OFF + row * AROW + q * 16) = v;
        }
    }
    __syncthreads();

    // ---- Extract Q fragments ----
    const uint32_t fragOff = (uint32_t)(lane & 15) * AROW + ((lane >> 4) * 16);
    const uint32_t wrowOff = (uint32_t)(w * 16) * AROW;
    uint32_t aq[4][4];
#pragma unroll
    for (int ks = 0; ks < 4; ks++)
        LDSM4(aq[ks][0], aq[ks][1], aq[ks][2], aq[ks][3],
              sb + QP_OFF + wrowOff + fragOff + ks * 32);

    float m0 = -1e30f, m1 = -1e30f, l0 = 0.f, l1 = 0.f;
    float o[8][4];
#pragma unroll
    for (int nt = 0; nt < 8; nt++)
#pragma unroll
        for (int k = 0; k < 4; k++) o[nt][k] = 0.f;

    const uint32_t bOffK = (uint32_t)(((lane >> 4) << 3) + (lane & 7)) * AROW
                         + (((lane >> 3) & 1) * 16);
    const uint32_t vOffT = (uint32_t)(lane & 15) * AROW + ((lane >> 4) * 16);

    auto loadKV = [&](int kt, int stg) {
        const __nv_bfloat16* Kg = qkv + (size_t)(b * SS + kt * 64) * D3 + DD + h * HD;
        const __nv_bfloat16* Vg = qkv + (size_t)(b * SS + kt * 64) * D3 + 2 * DD + h * HD;
        const uint32_t kbase = sb + K_OFF + stg * (64 * AROW);
        const uint32_t vbase = sb + V_OFF + stg * (64 * AROW);
#pragma unroll
        for (int t = 0; t < 4; t++) {
            const int idx = tid + t * 128;
            const int row = idx >> 3, q = idx & 7;
            const uint32_t off = (uint32_t)row * AROW + q * 16;
            cp16(kbase + off, Kg + (size_t)row * D3 + q * 8);
            cp16(vbase + off, Vg + (size_t)row * D3 + q * 8);
        }
        {
            const int delta = tid - 63 + kt * 64 - q0;
            ((float*)(smc + BIA_OFF))[stg * 128 + tid] =
                rpb[(size_t)(delta + SS - 1) * HH + h] * LOG2E;
        }
        CP_COMMIT();
    };

    loadKV(0, 0);

    for (int kt = 0; kt <= qt; kt++) {
        const int st = kt & 1;
        if (kt < qt) { loadKV(kt + 1, st ^ 1); CP_WAIT1(); }
        else         { CP_WAIT0(); }
        __syncthreads();

        const uint32_t kbase = sb + K_OFF + st * (64 * AROW);
        const uint32_t vbase = sb + V_OFF + st * (64 * AROW);
        const float* bsp = (const float*)(smc + BIA_OFF) + st * 128;
        const bool diag = (kt == qt);

        // ---- S = Q @ K^T ----
        float s[8][4];
#pragma unroll
        for (int nt = 0; nt < 8; nt++)
#pragma unroll
            for (int k = 0; k < 4; k++) s[nt][k] = 0.f;

#pragma unroll
        for (int ks = 0; ks < 4; ks++) {
            uint32_t bq[4][4];
#pragma unroll
            for (int p = 0; p < 4; p++)
                LDSM4(bq[p][0], bq[p][1], bq[p][2], bq[p][3],
                      kbase + bOffK + (uint32_t)p * 16 * AROW + ks * 32);
#pragma unroll
            for (int p = 0; p < 4; p++) {
                mma_bf16(s[2 * p    ], aq[ks], bq[p][0], bq[p][1]);
                mma_bf16(s[2 * p + 1], aq[ks], bq[p][2], bq[p][3]);
            }
        }

        // ---- scale + bias + causal mask + tile max ----
        float tm0 = -1e30f, tm1 = -1e30f;
#pragma unroll
        for (int nt = 0; nt < 8; nt++) {
            const int col = nt * 8 + c * 2;
            s[nt][0] = fmaf(s[nt][0], CF, bsp[col     - r0 + 63]);
            s[nt][1] = fmaf(s[nt][1], CF, bsp[col + 1 - r0 + 63]);
            s[nt][2] = fmaf(s[nt][2], CF, bsp[col     - r1 + 63]);
            s[nt][3] = fmaf(s[nt][3], CF, bsp[col + 1 - r1 + 63]);
            if (diag) {
                if (col     > r0) s[nt][0] = -1e30f;
                if (col + 1 > r0) s[nt][1] = -1e30f;
                if (col     > r1) s[nt][2] = -1e30f;
                if (col + 1 > r1) s[nt][3] = -1e30f;
            }
            tm0 = fmaxf(tm0, fmaxf(s[nt][0], s[nt][1]));
            tm1 = fmaxf(tm1, fmaxf(s[nt][2], s[nt][3]));
        }
        tm0 = fmaxf(tm0, __shfl_xor_sync(0xffffffffu, tm0, 1));
        tm0 = fmaxf(tm0, __shfl_xor_sync(0xffffffffu, tm0, 2));
        tm1 = fmaxf(tm1, __shfl_xor_sync(0xffffffffu, tm1, 1));
        tm1 = fmaxf(tm1, __shfl_xor_sync(0xffffffffu, tm1, 2));

        const float mn0 = fmaxf(m0, tm0);
        const float mn1 = fmaxf(m1, tm1);
        const float alpha0 = ex2f(m0 - mn0);
        const float alpha1 = ex2f(m1 - mn1);
        m0 = mn0; m1 = mn1;

        // ---- P = 2^(s-m) packed straight into A-fragments; row sums ----
        uint32_t pp0[8], pp1[8];
        float sum0 = 0.f, sum1 = 0.f;
#pragma unroll
        for (int nt = 0; nt < 8; nt++) {
            float p0 = ex2f(s[nt][0] - mn0);
            float p1 = ex2f(s[nt][1] - mn0);
            float p2 = ex2f(s[nt][2] - mn1);
            float p3 = ex2f(s[nt][3] - mn1);
            sum0 += p0 + p1;
            sum1 += p2 + p3;
            pp0[nt] = pack_bf16x2(p0, p1);
            pp1[nt] = pack_bf16x2(p2, p3);
        }
        sum0 += __shfl_xor_sync(0xffffffffu, sum0, 1);
        sum0 += __shfl_xor_sync(0xffffffffu, sum0, 2);
        sum1 += __shfl_xor_sync(0xffffffffu, sum1, 1);
        sum1 += __shfl_xor_sync(0xffffffffu, sum1, 2);
        l0 = l0 * alpha0 + sum0;
        l1 = l1 * alpha1 + sum1;

#pragma unroll
        for (int nt = 0; nt < 8; nt++) {
            o[nt][0] *= alpha0; o[nt][1] *= alpha0;
            o[nt][2] *= alpha1; o[nt][3] *= alpha1;
        }

        // ---- O += P @ V ----
#pragma unroll
        for (int ks = 0; ks < 4; ks++) {
            uint32_t ap[4] = { pp0[2 * ks], pp1[2 * ks], pp0[2 * ks + 1], pp1[2 * ks + 1] };
            uint32_t bv[4][4];
#pragma unroll
            for (int p = 0; p < 4; p++)
                LDSM4T(bv[p][0], bv[p][1], bv[p][2], bv[p][3],
                       vbase + vOffT + (uint32_t)ks * 16 * AROW + p * 32);
#pragma unroll
            for (int p = 0; p < 4; p++) {
                mma_bf16(o[2 * p    ], ap, bv[p][0], bv[p][1]);
                mma_bf16(o[2 * p + 1], ap, bv[p][2], bv[p][3]);
            }
        }
        __syncthreads();
    }

    // ---- Normalize + write bf16 ----
    const float inv0 = 1.f / l0;
    const float inv1 = 1.f / l1;
    const size_t base0 = (size_t)(b * SS + q0 + r0) * DD + h * HD;
    const size_t base1 = (size_t)(b * SS + q0 + r1) * DD + h * HD;
#pragma unroll
    for (int nt = 0; nt < 8; nt++) {
        const int col = nt * 8 + c * 2;
        *(uint32_t*)(obuf + base0 + col) = pack_bf16x2(o[nt][0] * inv0, o[nt][1] * inv0);
        *(uint32_t*)(obuf + base1 + col) = pack_bf16x2(o[nt][2] * inv1, o[nt][3] * inv1);
    }
}

// ---------------------------------------------------------------------------
// LayerNorm over D=1024
// ---------------------------------------------------------------------------
__global__ __launch_bounds__(256) void layernorm_k(
    const float* __restrict__ y, const float* __restrict__ g,
    const float* __restrict__ bta, float* __restrict__ out)
{
    const int row = blockIdx.x;
    const int t = threadIdx.x;
    const float4 v = *(const float4*)(y + (size_t)row * DD + t * 4);

    float s  = v.x + v.y + v.z + v.w;
    float sq = v.x * v.x + v.y * v.y + v.z * v.z + v.w * v.w;
#pragma unroll
    for (int off = 16; off > 0; off >>= 1) {
        s  += __shfl_xor_sync(0xffffffffu, s, off);
        sq += __shfl_xor_sync(0xffffffffu, sq, off);
    }
    __shared__ float ss[8], sqq[8];
    if ((t & 31) == 0) { ss[t >> 5] = s; sqq[t >> 5] = sq; }
    __syncthreads();
    float tot = 0.f, totq = 0.f;
#pragma unroll
    for (int i = 0; i < 8; i++) { tot += ss[i]; totq += sqq[i]; }
    const float mu  = tot * (1.f / DD);
    const float var = totq * (1.f / DD) - mu * mu;
    const float r   = rsqrtf(var + LN_EPS);

    const float4 gg = *(const float4*)(g + t * 4);
    const float4 bb = *(const float4*)(bta + t * 4);
    float4 o4;
    o4.x = (v.x - mu) * r * gg.x + bb.x;
    o4.y = (v.y - mu) * r * gg.y + bb.y;
    o4.z = (v.z - mu) * r * gg.z + bb.z;
    o4.w = (v.w - mu) * r * gg.w + bb.w;
    *(float4*)(out + (size_t)row * DD + t * 4) = o4;
}

// ---------------------------------------------------------------------------
// Launch
// ---------------------------------------------------------------------------
extern "C" void kernel_launch(void* const* d_in, const int* in_sizes, int n_in,
                              void* d_out, int out_size)
{
    const float* x      = (const float*)d_in[0];
    const float* W_w    = (const float*)d_in[1];
    const float* W_b    = (const float*)d_in[2];
    const float* proj_w = (const float*)d_in[3];
    const float* proj_b = (const float*)d_in[4];
    const float* ln_g   = (const float*)d_in[5];
    const float* ln_b   = (const float*)d_in[6];
    const float* rpb    = (const float*)d_in[7];
    float* out = (float*)d_out;

    float *ybuf;
    __nv_bfloat16 *qkvb, *xb, *wb, *pwb, *ob;
    cudaGetSymbolAddress((void**)&qkvb, g_qkvb);
    cudaGetSymbolAddress((void**)&ybuf, g_y);
    cudaGetSymbolAddress((void**)&xb,  g_xb);
    cudaGetSymbolAddress((void**)&wb,  g_wb);
    cudaGetSymbolAddress((void**)&pwb, g_pwb);
    cudaGetSymbolAddress((void**)&ob,  g_ob);

    cudaFuncSetAttribute(gemm_bf16, cudaFuncAttributeMaxDynamicSharedMemorySize, GEMM_SMEM);
    cudaFuncSetAttribute(attn_bf16, cudaFuncAttributeMaxDynamicSharedMemorySize, ATTN_SMEM);

    // 0) Convert inputs to bf16 (single launch)
    cvt_bf16_all<<<(CVT_N4_TOT + 255) / 256, 256>>>(x, W_w, proj_w, xb, wb, pwb);

    // 1) QKV projection -> bf16 output
    {
        dim3 grid(D3 / 128, MROWS / 128);
        gemm_bf16<<<grid, 256, GEMM_SMEM>>>(xb, wb, W_b, nullptr,
                                            nullptr, qkvb, MROWS, D3, DD);
    }

    // 2) Flash attention (descending-qt order)
    {
        dim3 grid(SS / 64, HH, BB);
        attn_bf16<<<grid, 128, ATTN_SMEM>>>(qkvb, rpb, ob);
    }

    // 3) Output projection + residual -> fp32
    {
        dim3 grid(DD / 128, MROWS / 128);
        gemm_bf16<<<grid, 256, GEMM_SMEM>>>(ob, pwb, proj_b, x,
                                            ybuf, nullptr, MROWS, DD, DD);
    }

    // 4) LayerNorm
    layernorm_k<<<MROWS, 256>>>(ybuf, ln_g, ln_b, out);
}

// round 14
// speedup vs baseline: 1.0456x; 1.0456x over previous
#include <cuda_runtime.h>
#include <cuda_bf16.h>
#include <cstdint>

// Problem constants
#define BB 2
#define SS 2048
#define DD 1024
#define HH 16
#define HD 64
#define D3 3072
#define MROWS (BB * SS)          // 4096
#define SCALE 0.03125f           // 1/sqrt(1024)
#define LOG2E 1.4426950408889634f
#define LN_EPS 1e-5f

// ---------------------------------------------------------------------------
// Scratch (no allocation allowed -> __device__ globals)
// ---------------------------------------------------------------------------
__device__ __nv_bfloat16 g_qkvb[MROWS * D3];   // 24 MB (QKV, bf16)
__device__ float g_y[MROWS * DD];              // 16 MB (proj + residual, fp32)
__device__ __nv_bfloat16 g_xb[MROWS * DD];     //  8 MB (x, bf16)
__device__ __nv_bfloat16 g_wb[D3 * DD];        //  6 MB (W_w, bf16)
__device__ __nv_bfloat16 g_pwb[DD * DD];       //  2 MB (proj_w, bf16)
__device__ __nv_bfloat16 g_ob[MROWS * DD];     //  8 MB (attention out, bf16)

// ---------------------------------------------------------------------------
// Portable helpers (sm_80+ only)
// ---------------------------------------------------------------------------
__device__ __forceinline__ uint32_t smem_u32(const void* p) {
    uint32_t a;
    asm("{ .reg .u64 t; cvta.to.shared.u64 t, %1; cvt.u32.u64 %0, t; }"
        : "=r"(a) : "l"(p));
    return a;
}

__device__ __forceinline__ void cp16(uint32_t dst, const void* src) {
    asm volatile("cp.async.ca.shared.global [%0], [%1], 16;"
                 :: "r"(dst), "l"(src) : "memory");
}
#define CP_COMMIT() asm volatile("cp.async.commit_group;" ::: "memory")
#define CP_WAIT0()  asm volatile("cp.async.wait_group 0;" ::: "memory")

__device__ __forceinline__ float ex2f(float x) {
    float r;
    asm("ex2.approx.f32 %0, %1;" : "=f"(r) : "f"(x));
    return r;
}

__device__ __forceinline__ void mma_bf16(
    float* c, const uint32_t* a, uint32_t b0, uint32_t b1)
{
    asm volatile(
        "mma.sync.aligned.m16n8k16.row.col.f32.bf16.bf16.f32 "
        "{%0,%1,%2,%3}, {%4,%5,%6,%7}, {%8,%9}, {%0,%1,%2,%3};"
        : "+f"(c[0]), "+f"(c[1]), "+f"(c[2]), "+f"(c[3])
        : "r"(a[0]), "r"(a[1]), "r"(a[2]), "r"(a[3]),
          "r"(b0), "r"(b1));
}

#define LDSM4(r0, r1, r2, r3, addr) \
    asm volatile("ldmatrix.sync.aligned.m8n8.x4.shared.b16 {%0,%1,%2,%3}, [%4];" \
        : "=r"(r0), "=r"(r1), "=r"(r2), "=r"(r3) : "r"(addr))

#define LDSM4T(r0, r1, r2, r3, addr) \
    asm volatile("ldmatrix.sync.aligned.m8n8.x4.trans.shared.b16 {%0,%1,%2,%3}, [%4];" \
        : "=r"(r0), "=r"(r1), "=r"(r2), "=r"(r3) : "r"(addr))

__device__ __forceinline__ uint32_t pack_bf16x2(float lo, float hi) {
    __nv_bfloat162 h = __floats2bfloat162_rn(lo, hi);
    return *(uint32_t*)&h;
}

// ---------------------------------------------------------------------------
// fp32 -> bf16 conversion, all three inputs in ONE launch
// ---------------------------------------------------------------------------
#define CVT_N4_X  (MROWS * DD / 4)
#define CVT_N4_W  (D3 * DD / 4)
#define CVT_N4_PW (DD * DD / 4)
#define CVT_N4_TOT (CVT_N4_X + CVT_N4_W + CVT_N4_PW)

__global__ __launch_bounds__(256) void cvt_bf16_all(
    const float* __restrict__ x, const float* __restrict__ w,
    const float* __restrict__ pw,
    __nv_bfloat16* __restrict__ xb, __nv_bfloat16* __restrict__ wb,
    __nv_bfloat16* __restrict__ pwb)
{
    int i = blockIdx.x * 256 + threadIdx.x;
    if (i >= CVT_N4_TOT) return;
    const float* in;
    __nv_bfloat16* out;
    if (i < CVT_N4_X)                 { in = x;  out = xb; }
    else if (i < CVT_N4_X + CVT_N4_W) { in = w;  out = wb;  i -= CVT_N4_X; }
    else                              { in = pw; out = pwb; i -= CVT_N4_X + CVT_N4_W; }
    float4 v = *(const float4*)(in + (size_t)i * 4);
    uint2 u;
    u.x = pack_bf16x2(v.x, v.y);
    u.y = pack_bf16x2(v.z, v.w);
    *(uint2*)(out + (size_t)i * 4) = u;
}

// ===========================================================================
// BF16 mma.sync GEMM: CTA 128x128, BK=64, 8 warps (4M x 2N), warp 32x64.
// 2-stage cp.async, ONE barrier per chunk:
//   wait(own copies) -> barrier -> prefetch next (safe overwrite) -> compute.
// ===========================================================================
#define BKB 64
#define GROW 144
#define GT_BYTES (128 * GROW)          // 18432 per tile
#define GEMM_SMEM (4 * GT_BYTES)       // 73728

__global__ __launch_bounds__(256) void gemm_bf16(
    const __nv_bfloat16* __restrict__ A, const __nv_bfloat16* __restrict__ W,
    const float* __restrict__ bias, const float* __restrict__ resid,
    float* __restrict__ C, __nv_bfloat16* __restrict__ Cb,
    int M, int N, int K)
{
    extern __shared__ char smc[];
    const uint32_t sb = smem_u32(smc);
    const uint32_t sA[2] = { sb,            sb + 2 * GT_BYTES };
    const uint32_t sB[2] = { sb + GT_BYTES, sb + 3 * GT_BYTES };

    const int tid  = threadIdx.x;
    const int lane = tid & 31;
    const int wid  = tid >> 5;
    const int g    = lane >> 2;
    const int c    = lane & 3;
    const int wm0  = (wid & 3) * 32;
    const int wn0  = (wid >> 2) * 64;
    const int m0   = blockIdx.y * 128;
    const int n0   = blockIdx.x * 128;

    const uint32_t aOff = (uint32_t)(wm0 + (lane & 15)) * GROW + ((lane >> 4) * 16);
    const uint32_t bOff = (uint32_t)(wn0 + ((lane >> 4) << 3) + (lane & 7)) * GROW
                        + (((lane >> 3) & 1) * 16);

    float acc[2][8][4];
#pragma unroll
    for (int mt = 0; mt < 2; mt++)
#pragma unroll
        for (int nt = 0; nt < 8; nt++)
#pragma unroll
            for (int k = 0; k < 4; k++) acc[mt][nt][k] = 0.f;

    const int nch = K / BKB;

    auto load_chunk = [&](int i, int st) {
        const __nv_bfloat16* Ag = A + (size_t)m0 * K + i * BKB;
        const __nv_bfloat16* Wg = W + (size_t)n0 * K + i * BKB;
#pragma unroll
        for (int t = 0; t < 4; t++) {
            const int idx = tid + t * 256;
            const int row = idx >> 3;
            const int q   = idx & 7;
            const uint32_t off = (uint32_t)row * GROW + q * 16;
            cp16(sA[st] + off, Ag + (size_t)row * K + q * 8);
            cp16(sB[st] + off, Wg + (size_t)row * K + q * 8);
        }
        CP_COMMIT();
    };

    load_chunk(0, 0);

    int st = 0;
    for (int i = 0; i < nch; i++) {
        CP_WAIT0();            // own copies of chunk i done (only pending group)
        __syncthreads();       // all waits done (visibility) + all compute(i-1) done
        if (i + 1 < nch) load_chunk(i + 1, st ^ 1);   // writes stage read in i-1: safe

        const uint32_t aBase = sA[st] + aOff;
        const uint32_t bBase = sB[st] + bOff;
#pragma unroll
        for (int kk = 0; kk < 4; kk++) {
            uint32_t a0[4], a1[4];
            LDSM4(a0[0], a0[1], a0[2], a0[3], aBase + kk * 32);
            LDSM4(a1[0], a1[1], a1[2], a1[3], aBase + kk * 32 + 16 * GROW);
            uint32_t bq[4][4];
#pragma unroll
            for (int p = 0; p < 4; p++)
                LDSM4(bq[p][0], bq[p][1], bq[p][2], bq[p][3],
                      bBase + (uint32_t)p * 16 * GROW + kk * 32);
#pragma unroll
            for (int p = 0; p < 4; p++) {
                mma_bf16(acc[0][2 * p    ], a0, bq[p][0], bq[p][1]);
                mma_bf16(acc[0][2 * p + 1], a0, bq[p][2], bq[p][3]);
                mma_bf16(acc[1][2 * p    ], a1, bq[p][0], bq[p][1]);
                mma_bf16(acc[1][2 * p + 1], a1, bq[p][2], bq[p][3]);
            }
        }
        st ^= 1;
    }

    // Epilogue
#pragma unroll
    for (int mt = 0; mt < 2; mt++) {
#pragma unroll
        for (int hrow = 0; hrow < 2; hrow++) {
            const int m = m0 + wm0 + mt * 16 + g + hrow * 8;
#pragma unroll
            for (int nt = 0; nt < 8; nt++) {
                const int col = n0 + wn0 + nt * 8 + c * 2;
                float2 bi = *(const float2*)(bias + col);
                float2 v;
                v.x = acc[mt][nt][hrow * 2 + 0] + bi.x;
                v.y = acc[mt][nt][hrow * 2 + 1] + bi.y;
                if (resid) {
                    float2 r = *(const float2*)(resid + (size_t)m * N + col);
                    v.x += r.x; v.y += r.y;
                }
                if (Cb) {
                    uint32_t hh = pack_bf16x2(v.x, v.y);
                    *(uint32_t*)(Cb + (size_t)m * N + col) = hh;
                } else {
                    *(float2*)(C + (size_t)m * N + col) = v;
                }
            }
        }
    }
}

// ===========================================================================
// BF16 tensor-core flash attention (P in registers), descending-qt order,
// ONE barrier per kt-iteration (wait -> barrier -> prefetch -> compute).
// ===========================================================================
#define AROW 144
#define QP_OFF 0
#define K_OFF  (64 * AROW)
#define V_OFF  (K_OFF + 2 * 64 * AROW)
#define BIA_OFF (V_OFF + 2 * 64 * AROW)
#define ATTN_SMEM (BIA_OFF + 2 * 128 * 4)  // 47104 bytes

__global__ __launch_bounds__(128) void attn_bf16(
    const __nv_bfloat16* __restrict__ qkv, const float* __restrict__ rpb,
    __nv_bfloat16* __restrict__ obuf)
{
    extern __shared__ char smc[];
    const uint32_t sb = smem_u32(smc);

    const int qt = (SS / 64 - 1) - blockIdx.x;
    const int h  = blockIdx.y;
    const int b  = blockIdx.z;
    const int tid = threadIdx.x;
    const int w    = tid >> 5;
    const int lane = tid & 31;
    const int g    = lane >> 2;
    const int c    = lane & 3;
    const int q0   = qt * 64;
    const int r0   = w * 16 + g;
    const int r1   = r0 + 8;
    const float CF = SCALE * LOG2E;

    // ---- Load Q tile ----
    {
        const __nv_bfloat16* Qg = qkv + (size_t)(b * SS + q0) * D3 + h * HD;
#pragma unroll
        for (int t = 0; t < 4; t++) {
            const int idx = tid + t * 128;
            const int row = idx >> 3, q = idx & 7;
            uint4 v = *(const uint4*)(Qg + (size_t)row * D3 + q * 8);
            *(uint4*)(smc + QP_OFF + row * AROW + q * 16) = v;
        }
    }
    __syncthreads();

    // ---- Extract Q fragments ----
    const uint32_t fragOff = (uint32_t)(lane & 15) * AROW + ((lane >> 4) * 16);
    const uint32_t wrowOff = (uint32_t)(w * 16) * AROW;
    uint32_t aq[4][4];
#pragma unroll
    for (int ks = 0; ks < 4; ks++)
        LDSM4(aq[ks][0], aq[ks][1], aq[ks][2], aq[ks][3],
              sb + QP_OFF + wrowOff + fragOff + ks * 32);

    float m0 = -1e30f, m1 = -1e30f, l0 = 0.f, l1 = 0.f;
    float o[8][4];
#pragma unroll
    for (int nt = 0; nt < 8; nt++)
#pragma unroll
        for (int k = 0; k < 4; k++) o[nt][k] = 0.f;

    const uint32_t bOffK = (uint32_t)(((lane >> 4) << 3) + (lane & 7)) * AROW
                         + (((lane >> 3) & 1) * 16);
    const uint32_t vOffT = (uint32_t)(lane & 15) * AROW + ((lane >> 4) * 16);

    auto loadKV = [&](int kt, int stg) {
        const __nv_bfloat16* Kg = qkv + (size_t)(b * SS + kt * 64) * D3 + DD + h * HD;
        const __nv_bfloat16* Vg = qkv + (size_t)(b * SS + kt * 64) * D3 + 2 * DD + h * HD;
        const uint32_t kbase = sb + K_OFF + stg * (64 * AROW);
        const uint32_t vbase = sb + V_OFF + stg * (64 * AROW);
#pragma unroll
        for (int t = 0; t < 4; t++) {
            const int idx = tid + t * 128;
            const int row = idx >> 3, q = idx & 7;
            const uint32_t off = (uint32_t)row * AROW + q * 16;
            cp16(kbase + off, Kg + (size_t)row * D3 + q * 8);
            cp16(vbase + off, Vg + (size_t)row * D3 + q * 8);
        }
        {
            const int delta = tid - 63 + kt * 64 - q0;
            ((float*)(smc + BIA_OFF))[stg * 128 + tid] =
                rpb[(size_t)(delta + SS - 1) * HH + h] * LOG2E;
        }
        CP_COMMIT();
    };

    loadKV(0, 0);

    int st = 0;
    for (int kt = 0; kt <= qt; kt++) {
        CP_WAIT0();            // own copies of tile kt done
        __syncthreads();       // visibility + stage-overwrite protection
        if (kt < qt) loadKV(kt + 1, st ^ 1);

        const uint32_t kbase = sb + K_OFF + st * (64 * AROW);
        const uint32_t vbase = sb + V_OFF + st * (64 * AROW);
        const float* bsp = (const float*)(smc + BIA_OFF) + st * 128;
        const bool diag = (kt == qt);

        // ---- S = Q @ K^T ----
        float s[8][4];
#pragma unroll
        for (int nt = 0; nt < 8; nt++)
#pragma unroll
            for (int k = 0; k < 4; k++) s[nt][k] = 0.f;

#pragma unroll
        for (int ks = 0; ks < 4; ks++) {
            uint32_t bq[4][4];
#pragma unroll
            for (int p = 0; p < 4; p++)
                LDSM4(bq[p][0], bq[p][1], bq[p][2], bq[p][3],
                      kbase + bOffK + (uint32_t)p * 16 * AROW + ks * 32);
#pragma unroll
            for (int p = 0; p < 4; p++) {
                mma_bf16(s[2 * p    ], aq[ks], bq[p][0], bq[p][1]);
                mma_bf16(s[2 * p + 1], aq[ks], bq[p][2], bq[p][3]);
            }
        }

        // ---- scale + bias + causal mask + tile max ----
        float tm0 = -1e30f, tm1 = -1e30f;
#pragma unroll
        for (int nt = 0; nt < 8; nt++) {
            const int col = nt * 8 + c * 2;
            s[nt][0] = fmaf(s[nt][0], CF, bsp[col     - r0 + 63]);
            s[nt][1] = fmaf(s[nt][1], CF, bsp[col + 1 - r0 + 63]);
            s[nt][2] = fmaf(s[nt][2], CF, bsp[col     - r1 + 63]);
            s[nt][3] = fmaf(s[nt][3], CF, bsp[col + 1 - r1 + 63]);
            if (diag) {
                if (col     > r0) s[nt][0] = -1e30f;
                if (col + 1 > r0) s[nt][1] = -1e30f;
                if (col     > r1) s[nt][2] = -1e30f;
                if (col + 1 > r1) s[nt][3] = -1e30f;
            }
            tm0 = fmaxf(tm0, fmaxf(s[nt][0], s[nt][1]));
            tm1 = fmaxf(tm1, fmaxf(s[nt][2], s[nt][3]));
        }
        tm0 = fmaxf(tm0, __shfl_xor_sync(0xffffffffu, tm0, 1));
        tm0 = fmaxf(tm0, __shfl_xor_sync(0xffffffffu, tm0, 2));
        tm1 = fmaxf(tm1, __shfl_xor_sync(0xffffffffu, tm1, 1));
        tm1 = fmaxf(tm1, __shfl_xor_sync(0xffffffffu, tm1, 2));

        const float mn0 = fmaxf(m0, tm0);
        const float mn1 = fmaxf(m1, tm1);
        const float alpha0 = ex2f(m0 - mn0);
        const float alpha1 = ex2f(m1 - mn1);
        m0 = mn0; m1 = mn1;

        // ---- P = 2^(s-m) packed straight into A-fragments; row sums ----
        uint32_t pp0[8], pp1[8];
        float sum0 = 0.f, sum1 = 0.f;
#pragma unroll
        for (int nt = 0; nt < 8; nt++) {
            float p0 = ex2f(s[nt][0] - mn0);
            float p1 = ex2f(s[nt][1] - mn0);
            float p2 = ex2f(s[nt][2] - mn1);
            float p3 = ex2f(s[nt][3] - mn1);
            sum0 += p0 + p1;
            sum1 += p2 + p3;
            pp0[nt] = pack_bf16x2(p0, p1);
            pp1[nt] = pack_bf16x2(p2, p3);
        }
        sum0 += __shfl_xor_sync(0xffffffffu, sum0, 1);
        sum0 += __shfl_xor_sync(0xffffffffu, sum0, 2);
        sum1 += __shfl_xor_sync(0xffffffffu, sum1, 1);
        sum1 += __shfl_xor_sync(0xffffffffu, sum1, 2);
        l0 = l0 * alpha0 + sum0;
        l1 = l1 * alpha1 + sum1;

#pragma unroll
        for (int nt = 0; nt < 8; nt++) {
            o[nt][0] *= alpha0; o[nt][1] *= alpha0;
            o[nt][2] *= alpha1; o[nt][3] *= alpha1;
        }

        // ---- O += P @ V ----
#pragma unroll
        for (int ks = 0; ks < 4; ks++) {
            uint32_t ap[4] = { pp0[2 * ks], pp1[2 * ks], pp0[2 * ks + 1], pp1[2 * ks + 1] };
            uint32_t bv[4][4];
#pragma unroll
            for (int p = 0; p < 4; p++)
                LDSM4T(bv[p][0], bv[p][1], bv[p][2], bv[p][3],
                       vbase + vOffT + (uint32_t)ks * 16 * AROW + p * 32);
#pragma unroll
            for (int p = 0; p < 4; p++) {
                mma_bf16(o[2 * p    ], ap, bv[p][0], bv[p][1]);
                mma_bf16(o[2 * p + 1], ap, bv[p][2], bv[p][3]);
            }
        }
        st ^= 1;
    }

    // ---- Normalize + write bf16 ----
    const float inv0 = 1.f / l0;
    const float inv1 = 1.f / l1;
    const size_t base0 = (size_t)(b * SS + q0 + r0) * DD + h * HD;
    const size_t base1 = (size_t)(b * SS + q0 + r1) * DD + h * HD;
#pragma unroll
    for (int nt = 0; nt < 8; nt++) {
        const int col = nt * 8 + c * 2;
        *(uint32_t*)(obuf + base0 + col) = pack_bf16x2(o[nt][0] * inv0, o[nt][1] * inv0);
        *(uint32_t*)(obuf + base1 + col) = pack_bf16x2(o[nt][2] * inv1, o[nt][3] * inv1);
    }
}

// ---------------------------------------------------------------------------
// LayerNorm over D=1024
// ---------------------------------------------------------------------------
__global__ __launch_bounds__(256) void layernorm_k(
    const float* __restrict__ y, const float* __restrict__ g,
    const float* __restrict__ bta, float* __restrict__ out)
{
    const int row = blockIdx.x;
    const int t = threadIdx.x;
    const float4 v = *(const float4*)(y + (size_t)row * DD + t * 4);

    float s  = v.x + v.y + v.z + v.w;
    float sq = v.x * v.x + v.y * v.y + v.z * v.z + v.w * v.w;
#pragma unroll
    for (int off = 16; off > 0; off >>= 1) {
        s  += __shfl_xor_sync(0xffffffffu, s, off);
        sq += __shfl_xor_sync(0xffffffffu, sq, off);
    }
    __shared__ float ss[8], sqq[8];
    if ((t & 31) == 0) { ss[t >> 5] = s; sqq[t >> 5] = sq; }
    __syncthreads();
    float tot = 0.f, totq = 0.f;
#pragma unroll
    for (int i = 0; i < 8; i++) { tot += ss[i]; totq += sqq[i]; }
    const float mu  = tot * (1.f / DD);
    const float var = totq * (1.f / DD) - mu * mu;
    const float r   = rsqrtf(var + LN_EPS);

    const float4 gg = *(const float4*)(g + t * 4);
    const float4 bb = *(const float4*)(bta + t * 4);
    float4 o4;
    o4.x = (v.x - mu) * r * gg.x + bb.x;
    o4.y = (v.y - mu) * r * gg.y + bb.y;
    o4.z = (v.z - mu) * r * gg.z + bb.z;
    o4.w = (v.w - mu) * r * gg.w + bb.w;
    *(float4*)(out + (size_t)row * DD + t * 4) = o4;
}

// ---------------------------------------------------------------------------
// Launch
// ---------------------------------------------------------------------------
extern "C" void kernel_launch(void* const* d_in, const int* in_sizes, int n_in,
                              void* d_out, int out_size)
{
    const float* x      = (const float*)d_in[0];
    const float* W_w    = (const float*)d_in[1];
    const float* W_b    = (const float*)d_in[2];
    const float* proj_w = (const float*)d_in[3];
    const float* proj_b = (const float*)d_in[4];
    const float* ln_g   = (const float*)d_in[5];
    const float* ln_b   = (const float*)d_in[6];
    const float* rpb    = (const float*)d_in[7];
    float* out = (float*)d_out;

    float *ybuf;
    __nv_bfloat16 *qkvb, *xb, *wb, *pwb, *ob;
    cudaGetSymbolAddress((void**)&qkvb, g_qkvb);
    cudaGetSymbolAddress((void**)&ybuf, g_y);
    cudaGetSymbolAddress((void**)&xb,  g_xb);
    cudaGetSymbolAddress((void**)&wb,  g_wb);
    cudaGetSymbolAddress((void**)&pwb, g_pwb);
    cudaGetSymbolAddress((void**)&ob,  g_ob);

    cudaFuncSetAttribute(gemm_bf16, cudaFuncAttributeMaxDynamicSharedMemorySize, GEMM_SMEM);
    cudaFuncSetAttribute(attn_bf16, cudaFuncAttributeMaxDynamicSharedMemorySize, ATTN_SMEM);

    // 0) Convert inputs to bf16 (single launch)
    cvt_bf16_all<<<(CVT_N4_TOT + 255) / 256, 256>>>(x, W_w, proj_w, xb, wb, pwb);

    // 1) QKV projection -> bf16 output
    {
        dim3 grid(D3 / 128, MROWS / 128);
        gemm_bf16<<<grid, 256, GEMM_SMEM>>>(xb, wb, W_b, nullptr,
                                            nullptr, qkvb, MROWS, D3, DD);
    }

    // 2) Flash attention (descending-qt order)
    {
        dim3 grid(SS / 64, HH, BB);
        attn_bf16<<<grid, 128, ATTN_SMEM>>>(qkvb, rpb, ob);
    }

    // 3) Output projection + residual -> fp32
    {
        dim3 grid(DD / 128, MROWS / 128);
        gemm_bf16<<<grid, 256, GEMM_SMEM>>>(ob, pwb, proj_b, x,
                                            ybuf, nullptr, MROWS, DD, DD);
    }

    // 4) LayerNorm
    layernorm_k<<<MROWS, 256>>>(ybuf, ln_g, ln_b, out);
}